// round 2
// baseline (speedup 1.0000x reference)
#include <cuda_runtime.h>
#include <math.h>

#define NB   8192
#define ND   128
#define MARGIN 0.2f
#define EPSL 1e-6f

#define BM 64
#define BN 128
#define BPAD 130      // B tile row pitch in floats (conflict-free reads, float2-alignable)

// Scratch (no allocations allowed)
__device__ float g_a1[NB];     // |e1_i|^2 + 2*eps*sum(e1_i) + D*eps^2
__device__ float g_c2[NB];     // |e2_j|^2 - 2*eps*sum(e2_j)
__device__ int   g_flag[NB];   // target == 1
__device__ float g_row[NB];    // per-anchor loss (weighted)

// ---------------------------------------------------------------------------
// Prep: per-row norms/sums for both matrices + flags. One warp per row.
// target is int32 (JAX x64 disabled: "int64" silently becomes int32).
// ---------------------------------------------------------------------------
__global__ void prep_kernel(const float* __restrict__ e1,
                            const float* __restrict__ e2,
                            const int* __restrict__ tgt) {
    int warp = (blockIdx.x * blockDim.x + threadIdx.x) >> 5;
    int lane = threadIdx.x & 31;
    if (warp >= NB) return;
    const float* r1 = e1 + (size_t)warp * ND;
    const float* r2 = e2 + (size_t)warp * ND;
    float n1 = 0.f, s1 = 0.f, n2 = 0.f, s2 = 0.f;
#pragma unroll
    for (int d = lane; d < ND; d += 32) {
        float a = r1[d], b = r2[d];
        n1 = fmaf(a, a, n1); s1 += a;
        n2 = fmaf(b, b, n2); s2 += b;
    }
#pragma unroll
    for (int o = 16; o; o >>= 1) {
        n1 += __shfl_xor_sync(0xFFFFFFFFu, n1, o);
        s1 += __shfl_xor_sync(0xFFFFFFFFu, s1, o);
        n2 += __shfl_xor_sync(0xFFFFFFFFu, n2, o);
        s2 += __shfl_xor_sync(0xFFFFFFFFu, s2, o);
    }
    if (lane == 0) {
        g_a1[warp] = n1 + 2.f * EPSL * s1 + (float)ND * EPSL * EPSL;
        g_c2[warp] = n2 - 2.f * EPSL * s2;
        g_flag[warp] = (tgt[warp] == 1) ? 1 : 0;
    }
}

// ---------------------------------------------------------------------------
// Main: fused Gram + masked row max/min. BM=64 rows per block, loop over all j
// in BN=128 column tiles with full K=128 resident in smem.
// 256 threads, each owns a 4x8 microtile (rows ty+16m, cols tx+16n).
// ---------------------------------------------------------------------------
__global__ __launch_bounds__(256, 1)
void main_kernel(const float* __restrict__ e1, const float* __restrict__ e2) {
    extern __shared__ float smem[];
    float* As = smem;                 // [BM][ND] row-major, no pad (A reads are broadcast)
    float* Bs = smem + BM * ND;       // [BN][BPAD]
    __shared__ float c2s[BN];
    __shared__ int   fls[BN];

    const int tid = threadIdx.x;
    const int tx = tid & 15;
    const int ty = tid >> 4;
    const int row0 = blockIdx.x * BM;

    // Load A tile: 64x128 floats = 2048 float4, 8 per thread. Coalesced.
    {
        const float4* gA = (const float4*)(e1 + (size_t)row0 * ND);
        float4* sA = (float4*)As;
#pragma unroll
        for (int k = 0; k < 8; ++k) sA[tid + 256 * k] = gA[tid + 256 * k];
    }

    float pmax[4], nmin[4];
#pragma unroll
    for (int m = 0; m < 4; ++m) { pmax[m] = -3.402823e38f; nmin[m] = 3.402823e38f; }

    for (int jt = 0; jt < NB / BN; ++jt) {
        __syncthreads();
        // Load B tile: 128x128 floats -> Bs[r][BPAD]. 4096 float4, 16/thread.
        {
            const float4* gB = (const float4*)(e2 + (size_t)jt * BN * ND);
#pragma unroll
            for (int k = 0; k < 16; ++k) {
                int idx = tid + 256 * k;        // float4 index 0..4095
                int r = idx >> 5;               // 32 float4 per row
                int c = (idx & 31) << 2;        // float column
                float4 v = gB[idx];
                float2* dst = (float2*)&Bs[r * BPAD + c];   // BPAD even -> 8B aligned
                dst[0] = make_float2(v.x, v.y);
                dst[1] = make_float2(v.z, v.w);
            }
            if (tid < BN) {
                c2s[tid] = g_c2[jt * BN + tid];
                fls[tid] = g_flag[jt * BN + tid];
            }
        }
        __syncthreads();

        float acc[4][8];
#pragma unroll
        for (int m = 0; m < 4; ++m)
#pragma unroll
            for (int n = 0; n < 8; ++n) acc[m][n] = 0.f;

#pragma unroll 8
        for (int d = 0; d < ND; ++d) {
            float a[4], b[8];
#pragma unroll
            for (int m = 0; m < 4; ++m) a[m] = As[(ty + 16 * m) * ND + d];
#pragma unroll
            for (int n = 0; n < 8; ++n) b[n] = Bs[(tx + 16 * n) * BPAD + d];
#pragma unroll
            for (int m = 0; m < 4; ++m)
#pragma unroll
                for (int n = 0; n < 8; ++n) acc[m][n] = fmaf(a[m], b[n], acc[m][n]);
        }

        // Masked running max/min of (c2[j] - 2*dot)
#pragma unroll
        for (int n = 0; n < 8; ++n) {
            int col = tx + 16 * n;
            float c2 = c2s[col];
            int f = fls[col];
#pragma unroll
            for (int m = 0; m < 4; ++m) {
                float v = c2 - 2.f * acc[m][n];
                if (f) pmax[m] = fmaxf(pmax[m], v);
                else   nmin[m] = fminf(nmin[m], v);
            }
        }
    }

    // Reduce across the 16 threads (tx) sharing each row, within 16-lane groups.
#pragma unroll
    for (int m = 0; m < 4; ++m) {
        float p = pmax[m], q = nmin[m];
#pragma unroll
        for (int o = 8; o; o >>= 1) {
            p = fmaxf(p, __shfl_xor_sync(0xFFFFFFFFu, p, o));
            q = fminf(q, __shfl_xor_sync(0xFFFFFFFFu, q, o));
        }
        if (tx == 0) {
            int row = row0 + ty + 16 * m;
            float res = 0.f;
            if (g_flag[row]) {
                float a1 = g_a1[row];
                float dp = sqrtf(fmaxf(a1 + p, 0.f));
                float dn = sqrtf(fmaxf(a1 + q, 0.f));
                res = fmaxf(dp - dn + MARGIN, 0.f);
            }
            g_row[row] = res;
        }
    }
}

// ---------------------------------------------------------------------------
// Finalize: deterministic reduction -> scalar mean over anchors.
// ---------------------------------------------------------------------------
__global__ void finalize_kernel(float* __restrict__ out) {
    __shared__ float ss[256];
    __shared__ float sw[256];
    float s = 0.f, w = 0.f;
    for (int i = threadIdx.x; i < NB; i += 256) {
        s += g_row[i];
        w += (float)g_flag[i];
    }
    ss[threadIdx.x] = s; sw[threadIdx.x] = w;
    __syncthreads();
#pragma unroll
    for (int o = 128; o; o >>= 1) {
        if (threadIdx.x < o) {
            ss[threadIdx.x] += ss[threadIdx.x + o];
            sw[threadIdx.x] += sw[threadIdx.x + o];
        }
        __syncthreads();
    }
    if (threadIdx.x == 0) out[0] = ss[0] / sw[0];
}

extern "C" void kernel_launch(void* const* d_in, const int* in_sizes, int n_in,
                              void* d_out, int out_size) {
    const float* e1 = (const float*)d_in[0];
    const float* e2 = (const float*)d_in[1];
    const int* tgt = (const int*)d_in[2];
    float* out = (float*)d_out;

    prep_kernel<<<NB / 8, 256>>>(e1, e2, tgt);

    size_t smem_bytes = (size_t)(BM * ND + BN * BPAD) * sizeof(float);
    cudaFuncSetAttribute(main_kernel, cudaFuncAttributeMaxDynamicSharedMemorySize,
                         (int)smem_bytes);
    main_kernel<<<NB / BM, 256, smem_bytes>>>(e1, e2);

    finalize_kernel<<<1, 256>>>(out);
}

// round 4
// speedup vs baseline: 6.2751x; 6.2751x over previous
#include <cuda_runtime.h>
#include <cuda_fp16.h>
#include <cstdint>
#include <math.h>

#define NB   8192
#define ND   128
#define MARGIN 0.2f
#define EPSL 1e-6f
#define NTILES 32          // column tiles per CTA (each 128 cols)

// ---------------- device scratch (no allocations allowed) -------------------
__device__ float  g_a1[NB];
__device__ float2 g_cpn[NB];    // (pos? c2 : -1e30, neg? c2 : +1e30)
__device__ int    g_flag[NB];
__device__ float  g_pm[2 * NB];
__device__ float  g_nm[2 * NB];
__device__ __align__(16) __half g_e1[NB * ND];
__device__ __align__(16) __half g_e2[NB * ND];

// ---------------- helpers ----------------------------------------------------
__device__ __forceinline__ uint32_t smem_u32(const void* p) {
    uint32_t a;
    asm("{ .reg .u64 t; cvta.to.shared.u64 t, %1; cvt.u32.u64 %0, t; }" : "=r"(a) : "l"(p));
    return a;
}
__device__ __forceinline__ void cp16(uint32_t saddr, const void* g) {
    asm volatile("cp.async.cg.shared.global [%0], [%1], 16;" :: "r"(saddr), "l"(g));
}
#define CP_COMMIT() asm volatile("cp.async.commit_group;" ::: "memory")
#define CP_WAIT1()  asm volatile("cp.async.wait_group 1;" ::: "memory")

#define LDSM4(r, addr) \
    asm volatile("ldmatrix.sync.aligned.m8n8.x4.shared.b16 {%0,%1,%2,%3}, [%4];" \
        : "=r"((r)[0]), "=r"((r)[1]), "=r"((r)[2]), "=r"((r)[3]) : "r"(addr))

__device__ __forceinline__ void mma16816(float* c, const uint32_t* a, uint32_t b0, uint32_t b1) {
    asm volatile("mma.sync.aligned.m16n8k16.row.col.f32.f16.f16.f32 "
        "{%0,%1,%2,%3}, {%4,%5,%6,%7}, {%8,%9}, {%0,%1,%2,%3};"
        : "+f"(c[0]), "+f"(c[1]), "+f"(c[2]), "+f"(c[3])
        : "r"(a[0]), "r"(a[1]), "r"(a[2]), "r"(a[3]), "r"(b0), "r"(b1));
}

// ---------------- prep: fp16 convert + row stats ----------------------------
__global__ void prep_kernel(const float* __restrict__ e1,
                            const float* __restrict__ e2,
                            const int* __restrict__ tgt) {
    int row = (blockIdx.x * blockDim.x + threadIdx.x) >> 5;
    int lane = threadIdx.x & 31;
    if (row >= NB) return;
    const float* r1 = e1 + (size_t)row * ND;
    const float* r2 = e2 + (size_t)row * ND;
    float n1 = 0.f, s1 = 0.f, n2 = 0.f, s2 = 0.f;
#pragma unroll
    for (int d = lane; d < ND; d += 32) {
        float a = r1[d], b = r2[d];
        g_e1[row * ND + d] = __float2half_rn(a);
        g_e2[row * ND + d] = __float2half_rn(b);
        n1 = fmaf(a, a, n1); s1 += a;
        n2 = fmaf(b, b, n2); s2 += b;
    }
#pragma unroll
    for (int o = 16; o; o >>= 1) {
        n1 += __shfl_xor_sync(0xFFFFFFFFu, n1, o);
        s1 += __shfl_xor_sync(0xFFFFFFFFu, s1, o);
        n2 += __shfl_xor_sync(0xFFFFFFFFu, n2, o);
        s2 += __shfl_xor_sync(0xFFFFFFFFu, s2, o);
    }
    if (lane == 0) {
        g_a1[row] = n1 + 2.f * EPSL * s1 + (float)ND * EPSL * EPSL;
        float c2 = n2 - 2.f * EPSL * s2;
        int f = (tgt[row] == 1);
        g_flag[row] = f;
        g_cpn[row] = make_float2(f ? c2 : -1e30f, f ? 1e30f : c2);
    }
}

// ---------------- main kernel ------------------------------------------------
// smem: A 32KB | B stage0 32KB | B stage1 32KB | cpn stage0 1KB | cpn stage1 1KB
#define SA      0
#define SB(s)   (32768 + (s) * 32768)
#define SC(s)   (98304 + (s) * 1024)
#define DSMEM   (98304 + 2048)

__device__ __forceinline__ void issue_tile(char* sm, uint32_t sbase, int stage,
                                           int tileIdx, int tid) {
    const uint4* gB = (const uint4*)g_e2 + (size_t)tileIdx * 128 * 16;
#pragma unroll
    for (int i = 0; i < 8; ++i) {
        int linear = tid + 256 * i;
        int r = linear >> 4, c = linear & 15;
        cp16(sbase + SB(stage) + r * 256 + ((c ^ (r & 7)) << 4), gB + linear);
    }
    if (tid < 64)
        cp16(sbase + SC(stage) + tid * 16,
             (const char*)(g_cpn + (size_t)tileIdx * 128) + tid * 16);
}

__global__ __launch_bounds__(256, 1) void main_kernel() {
    extern __shared__ char sm[];
    __shared__ float s_pm[2][128], s_nm[2][128];
    const uint32_t sbase = smem_u32(sm);
    const int tid = threadIdx.x;
    const int lane = tid & 31, wid = tid >> 5;
    const int wy = wid & 3, wx = wid >> 2;
    const int rb = blockIdx.x >> 1, half = blockIdx.x & 1;
    const int tile0 = half * NTILES;

    // Load A tile (128x128 fp16 -> swizzled smem), plain ld/st.
    {
        const uint4* gA = (const uint4*)g_e1 + (size_t)rb * 128 * 16;
#pragma unroll
        for (int i = 0; i < 8; ++i) {
            int linear = tid + 256 * i;
            int r = linear >> 4, c = linear & 15;
            *(uint4*)(sm + SA + r * 256 + ((c ^ (r & 7)) << 4)) = gA[linear];
        }
    }

    issue_tile(sm, sbase, 0, tile0 + 0, tid); CP_COMMIT();
    issue_tile(sm, sbase, 1, tile0 + 1, tid); CP_COMMIT();

    // Per-lane ldmatrix address precomputation.
    const int rA = lane & 15, hA = lane >> 4, xA = rA & 7;
    uint32_t baseA[2];
#pragma unroll
    for (int mb = 0; mb < 2; ++mb)
        baseA[mb] = sbase + SA + (wy * 32 + mb * 16 + rA) * 256;
    const int rB = (lane & 7) | ((lane >> 4) << 3);
    const int hB = (lane >> 3) & 1, xB = rB & 7;
    uint32_t rowB[4];
#pragma unroll
    for (int p = 0; p < 4; ++p)
        rowB[p] = (wx * 64 + p * 16 + rB) * 256;

    float pm[2][2], nm[2][2];
#pragma unroll
    for (int a = 0; a < 2; ++a)
#pragma unroll
        for (int b = 0; b < 2; ++b) { pm[a][b] = -3.402823e38f; nm[a][b] = 3.402823e38f; }

    for (int t = 0; t < NTILES; ++t) {
        const int st = t & 1;
        CP_WAIT1();
        __syncthreads();

        float acc[2][8][4];
#pragma unroll
        for (int mb = 0; mb < 2; ++mb)
#pragma unroll
            for (int nb = 0; nb < 8; ++nb)
#pragma unroll
                for (int v = 0; v < 4; ++v) acc[mb][nb][v] = 0.f;

        const uint32_t sbB = sbase + SB(st);
#pragma unroll
        for (int ks = 0; ks < 8; ++ks) {
            uint32_t a[2][4], b[4][4];
            uint32_t cA = (uint32_t)(((2 * ks + hA) ^ xA) << 4);
            LDSM4(a[0], baseA[0] + cA);
            LDSM4(a[1], baseA[1] + cA);
            uint32_t cB = (uint32_t)(((2 * ks + hB) ^ xB) << 4);
#pragma unroll
            for (int p = 0; p < 4; ++p) LDSM4(b[p], sbB + rowB[p] + cB);
#pragma unroll
            for (int mb = 0; mb < 2; ++mb)
#pragma unroll
                for (int p = 0; p < 4; ++p) {
                    mma16816(acc[mb][2 * p + 0], a[mb], b[p][0], b[p][1]);
                    mma16816(acc[mb][2 * p + 1], a[mb], b[p][2], b[p][3]);
                }
        }

        // Epilogue: masked running max/min of (cpn - 2*dot)
        const char* scp = sm + SC(st);
#pragma unroll
        for (int nb = 0; nb < 8; ++nb) {
            int c0 = wx * 64 + nb * 8 + (lane & 3) * 2;
            float2 p0 = *(const float2*)(scp + (size_t)c0 * 8);
            float2 p1 = *(const float2*)(scp + (size_t)(c0 + 1) * 8);
#pragma unroll
            for (int mb = 0; mb < 2; ++mb) {
                const float* A4 = acc[mb][nb];
                pm[mb][0] = fmaxf(pm[mb][0], fmaf(-2.f, A4[0], p0.x));
                pm[mb][0] = fmaxf(pm[mb][0], fmaf(-2.f, A4[1], p1.x));
                pm[mb][1] = fmaxf(pm[mb][1], fmaf(-2.f, A4[2], p0.x));
                pm[mb][1] = fmaxf(pm[mb][1], fmaf(-2.f, A4[3], p1.x));
                nm[mb][0] = fminf(nm[mb][0], fmaf(-2.f, A4[0], p0.y));
                nm[mb][0] = fminf(nm[mb][0], fmaf(-2.f, A4[1], p1.y));
                nm[mb][1] = fminf(nm[mb][1], fmaf(-2.f, A4[2], p0.y));
                nm[mb][1] = fminf(nm[mb][1], fmaf(-2.f, A4[3], p1.y));
            }
        }

        __syncthreads();
        if (t + 2 < NTILES) issue_tile(sm, sbase, st, tile0 + t + 2, tid);
        CP_COMMIT();
    }

    // Cross-lane reduction: quads share the same row set.
#pragma unroll
    for (int mb = 0; mb < 2; ++mb)
#pragma unroll
        for (int rh = 0; rh < 2; ++rh) {
            float p = pm[mb][rh], n = nm[mb][rh];
            p = fmaxf(p, __shfl_xor_sync(0xFFFFFFFFu, p, 1));
            p = fmaxf(p, __shfl_xor_sync(0xFFFFFFFFu, p, 2));
            n = fminf(n, __shfl_xor_sync(0xFFFFFFFFu, n, 1));
            n = fminf(n, __shfl_xor_sync(0xFFFFFFFFu, n, 2));
            if ((lane & 3) == 0) {
                int m = wy * 32 + mb * 16 + rh * 8 + (lane >> 2);
                s_pm[wx][m] = p;
                s_nm[wx][m] = n;
            }
        }
    __syncthreads();
    if (tid < 128) {
        g_pm[half * NB + rb * 128 + tid] = fmaxf(s_pm[0][tid], s_pm[1][tid]);
        g_nm[half * NB + rb * 128 + tid] = fminf(s_nm[0][tid], s_nm[1][tid]);
    }
}

// ---------------- finalize ---------------------------------------------------
__global__ void finalize_kernel(float* __restrict__ out) {
    __shared__ float ss[256], sw[256];
    float s = 0.f, w = 0.f;
    for (int i = threadIdx.x; i < NB; i += 256) {
        if (g_flag[i]) {
            float p = fmaxf(g_pm[i], g_pm[NB + i]);
            float n = fminf(g_nm[i], g_nm[NB + i]);
            float a1 = g_a1[i];
            float dp = sqrtf(fmaxf(a1 + p, 0.f));
            float dn = sqrtf(fmaxf(a1 + n, 0.f));
            s += fmaxf(dp - dn + MARGIN, 0.f);
            w += 1.f;
        }
    }
    ss[threadIdx.x] = s; sw[threadIdx.x] = w;
    __syncthreads();
#pragma unroll
    for (int o = 128; o; o >>= 1) {
        if (threadIdx.x < o) {
            ss[threadIdx.x] += ss[threadIdx.x + o];
            sw[threadIdx.x] += sw[threadIdx.x + o];
        }
        __syncthreads();
    }
    if (threadIdx.x == 0) out[0] = ss[0] / sw[0];
}

extern "C" void kernel_launch(void* const* d_in, const int* in_sizes, int n_in,
                              void* d_out, int out_size) {
    const float* e1 = (const float*)d_in[0];
    const float* e2 = (const float*)d_in[1];
    const int* tgt = (const int*)d_in[2];
    float* out = (float*)d_out;

    prep_kernel<<<NB / 8, 256>>>(e1, e2, tgt);

    cudaFuncSetAttribute(main_kernel, cudaFuncAttributeMaxDynamicSharedMemorySize, DSMEM);
    main_kernel<<<128, 256, DSMEM>>>();

    finalize_kernel<<<1, 256>>>(out);
}